// round 15
// baseline (speedup 1.0000x reference)
#include <cuda_runtime.h>
#include <cuda_bf16.h>
#include <cuda_fp16.h>
#include <cstdint>

// ---------------------------------------------------------------------------
// GCN: 4x GCNConv(128->128) + output linear(128->128), N=100000, E=1600000.
// Round 15: GEMM occupancy 3->4 CTAs/SM (launch_bounds(256,4), single-buffer
// fragments to fit 64 regs). Identical mma/ldsm mix — clean occupancy test.
// ---------------------------------------------------------------------------

#define NMAX 100096
#define EMAX 1600000
#define FDIM 128
#define SCAN_B 1024
#define MAXBLK 128
#define BM 64

__device__ __align__(16) __half g_t16[(size_t)NMAX * FDIM];   // conv GEMM out
__device__ __align__(16) __half g_h16[(size_t)NMAX * FDIM];   // aggregate out
__device__ __align__(16) __half g_x16[(size_t)NMAX * FDIM];   // fp16 input x
__device__ float g_deg[NMAX];
__device__ float g_dinv[NMAX];
__device__ int   g_cnt[NMAX];
__device__ int   g_rowptr[NMAX + 1];
__device__ int   g_cursor[NMAX];
__device__ int   g_srow[EMAX];
__device__ float g_snorm[EMAX];
__device__ int   g_bsum[MAXBLK];
__device__ int   g_boffs[MAXBLK];
__device__ __align__(16) __half g_w16[5 * 16384];

// ---------------- helpers ----------------

__device__ __forceinline__ uint32_t smem_u32(const void* p) {
    uint32_t a;
    asm("{ .reg .u64 t; cvta.to.shared.u64 t, %1; cvt.u32.u64 %0, t; }" : "=r"(a) : "l"(p));
    return a;
}

__device__ __forceinline__ void ldsm4(uint32_t& r0, uint32_t& r1, uint32_t& r2,
                                      uint32_t& r3, uint32_t addr) {
    asm volatile("ldmatrix.sync.aligned.m8n8.x4.shared.b16 {%0,%1,%2,%3}, [%4];"
                 : "=r"(r0), "=r"(r1), "=r"(r2), "=r"(r3) : "r"(addr));
}

__device__ __forceinline__ void mma16816h(float* c, const uint32_t* a,
                                          uint32_t b0, uint32_t b1) {
    asm volatile(
        "mma.sync.aligned.m16n8k16.row.col.f32.f16.f16.f32 "
        "{%0,%1,%2,%3}, {%4,%5,%6,%7}, {%8,%9}, {%0,%1,%2,%3};"
        : "+f"(c[0]), "+f"(c[1]), "+f"(c[2]), "+f"(c[3])
        : "r"(a[0]), "r"(a[1]), "r"(a[2]), "r"(a[3]), "r"(b0), "r"(b1));
}

__device__ __forceinline__ void cp16(uint32_t dst, const void* src) {
    asm volatile("cp.async.ca.shared.global [%0], [%1], 16;" :: "r"(dst), "l"(src));
}

__device__ __forceinline__ uint32_t swz(int r, int k) {
    return (uint32_t)((r << 8) + ((((k >> 3) ^ (r & 7)) << 4)) + ((k & 7) << 1));
}

// ---------------- x prep: fp32 -> fp16 ----------------

__global__ void k_xprep(const float* __restrict__ x, __half* __restrict__ x16,
                        int total4) {
    int i = blockIdx.x * blockDim.x + threadIdx.x;
    if (i >= total4) return;
    float4 v = reinterpret_cast<const float4*>(x)[i];
    __half2 p0 = __floats2half2_rn(v.x, v.y);
    __half2 p1 = __floats2half2_rn(v.z, v.w);
    uint2 o;
    o.x = *reinterpret_cast<uint32_t*>(&p0);
    o.y = *reinterpret_cast<uint32_t*>(&p1);
    reinterpret_cast<uint2*>(x16)[i] = o;
}

// ---------------- degree + histogram ----------------

__global__ void k_init(float* __restrict__ deg, int* __restrict__ cnt,
                       int* __restrict__ cur, int n) {
    int i = blockIdx.x * blockDim.x + threadIdx.x;
    if (i < n) { deg[i] = 1.0f; cnt[i] = 0; cur[i] = 0; }
}

__global__ void k_deg_hist(const int* __restrict__ col, const float* __restrict__ ew,
                           float* __restrict__ deg, int* __restrict__ cnt, int E) {
    int e = blockIdx.x * blockDim.x + threadIdx.x;
    if (e < E) {
        int c = col[e];
        atomicAdd(&deg[c], ew[e]);
        atomicAdd(&cnt[c], 1);
    }
}

__global__ void k_dinv(const float* __restrict__ deg, float* __restrict__ dinv, int n) {
    int i = blockIdx.x * blockDim.x + threadIdx.x;
    if (i < n) {
        float d = deg[i];
        dinv[i] = (d > 0.0f) ? rsqrtf(d) : 0.0f;
    }
}

// ---------------- 3-phase scan ----------------

__global__ void __launch_bounds__(SCAN_B) k_scan_local(
    const int* __restrict__ cnt, int* __restrict__ rowptr,
    int* __restrict__ bsum, int n)
{
    __shared__ int s[SCAN_B];
    const int tid = threadIdx.x;
    const int i = blockIdx.x * SCAN_B + tid;
    int v = (i < n) ? cnt[i] : 0;
    s[tid] = v;
    __syncthreads();
#pragma unroll
    for (int ofs = 1; ofs < SCAN_B; ofs <<= 1) {
        int t = (tid >= ofs) ? s[tid - ofs] : 0;
        __syncthreads();
        s[tid] += t;
        __syncthreads();
    }
    if (i < n) rowptr[i] = s[tid] - v;
    if (tid == SCAN_B - 1) bsum[blockIdx.x] = s[tid];
}

__global__ void __launch_bounds__(MAXBLK) k_scan_mid(
    const int* __restrict__ bsum, int* __restrict__ boffs, int nb)
{
    __shared__ int s[MAXBLK];
    const int tid = threadIdx.x;
    int v = (tid < nb) ? bsum[tid] : 0;
    s[tid] = v;
    __syncthreads();
#pragma unroll
    for (int ofs = 1; ofs < MAXBLK; ofs <<= 1) {
        int t = (tid >= ofs) ? s[tid - ofs] : 0;
        __syncthreads();
        s[tid] += t;
        __syncthreads();
    }
    if (tid < nb) boffs[tid] = s[tid] - v;
}

__global__ void __launch_bounds__(SCAN_B) k_scan_add(
    int* __restrict__ rowptr, const int* __restrict__ boffs, int n, int E)
{
    const int i = blockIdx.x * SCAN_B + threadIdx.x;
    if (i < n) rowptr[i] += boffs[blockIdx.x];
    if (i == 0) rowptr[n] = E;
}

// ---------------- counting-sort fill ----------------

__global__ void k_fill(const int* __restrict__ row, const int* __restrict__ col,
                       const float* __restrict__ ew, const float* __restrict__ dinv,
                       const int* __restrict__ rowptr, int* __restrict__ cur,
                       int* __restrict__ srow, float* __restrict__ snorm, int E) {
    int e = blockIdx.x * blockDim.x + threadIdx.x;
    if (e >= E) return;
    int r = row[e];
    int c = col[e];
    int pos = rowptr[c] + atomicAdd(&cur[c], 1);
    srow[pos] = r;
    snorm[pos] = dinv[r] * ew[e] * dinv[c];
}

// ---------------- weight prep: single fp16 ----------------

__device__ __forceinline__ void wprep_one(const float* W, __half* dst, int idx) {
    int n = idx >> 7, k = idx & 127;
    dst[n * 128 + k] = __float2half_rn(W[k * 128 + n]);   // B[n][k] = W[k][n]
}

__global__ void k_wprep(const float* __restrict__ W, __half* __restrict__ dst) {
    int idx = blockIdx.x * blockDim.x + threadIdx.x;
    if (idx >= 16384) return;
    wprep_one(W, dst, idx);
}

__global__ void k_wprep4(const float* __restrict__ W1, const float* __restrict__ W2,
                         const float* __restrict__ W3, const float* __restrict__ W4,
                         __half* __restrict__ base) {
    int idx = blockIdx.x * blockDim.x + threadIdx.x;
    if (idx >= 16384) return;
    const float* W = (blockIdx.y == 0) ? W1 : (blockIdx.y == 1) ? W2
                   : (blockIdx.y == 2) ? W3 : W4;
    wprep_one(W, base + (blockIdx.y + 1) * 16384, idx);
}

// ---------------- fp16 HMMA GEMM: C = A @ W ----------------
// A fp16 (16KB), W fp16 (32KB); single-buffered frags; 4 CTAs/SM.

__global__ void __launch_bounds__(256, 4) k_gemm_mma(
    const __half* __restrict__ A, const __half* __restrict__ w16,
    const float* __restrict__ bias, __half* __restrict__ Ch,
    float* __restrict__ Cf, int M, int outFloat)
{
    extern __shared__ char sm[];
    char* sA = sm;                    // 16KB
    char* sW = sm + 16384;            // 32KB

    const int tid = threadIdx.x;
    const int wid = tid >> 5;
    const int lane = tid & 31;
    const int rbase = blockIdx.x * BM;

    const uint32_t uA = smem_u32(sA);
    const uint32_t uW = smem_u32(sW);

    for (int i = tid; i < 2048; i += 256) {
        int r = i >> 4, c = i & 15;
        uint32_t doff = (uint32_t)((r << 8) + ((c ^ (r & 7)) << 4));
        cp16(uW + doff, w16 + r * 128 + c * 8);
    }
    for (int i = tid; i < 1024; i += 256) {
        int r = i >> 4, c = i & 15;
        int grow = rbase + r;
        if (grow < M) {
            uint32_t doff = (uint32_t)((r << 8) + ((c ^ (r & 7)) << 4));
            cp16(uA + doff, A + (size_t)grow * FDIM + c * 8);
        }
    }
    asm volatile("cp.async.commit_group;" ::: "memory");
    asm volatile("cp.async.wait_group 0;" ::: "memory");
    __syncthreads();

    const int warpRow = (wid & 1) * 32;
    const int warpCol = (wid >> 1) * 32;
    const int a_r = lane & 15;
    const int a_k = (lane >> 4) << 3;
    const int b_n = (lane & 7) + ((lane >> 4) << 3);
    const int b_k = ((lane >> 3) & 1) << 3;

    float c[2][4][4];
#pragma unroll
    for (int mi = 0; mi < 2; mi++)
#pragma unroll
        for (int ni = 0; ni < 4; ni++)
#pragma unroll
            for (int q = 0; q < 4; q++) c[mi][ni][q] = 0.0f;

    uint32_t a0[4], a1[4], b0[4], b1[4];

#pragma unroll
    for (int it = 0; it < 8; it++) {
        const int k0 = it << 4;
        ldsm4(a0[0], a0[1], a0[2], a0[3], uA + swz(warpRow + a_r,      k0 + a_k));
        ldsm4(a1[0], a1[1], a1[2], a1[3], uA + swz(warpRow + 16 + a_r, k0 + a_k));
        ldsm4(b0[0], b0[1], b0[2], b0[3], uW + swz(warpCol + b_n,      k0 + b_k));
        ldsm4(b1[0], b1[1], b1[2], b1[3], uW + swz(warpCol + 16 + b_n, k0 + b_k));
        mma16816h(c[0][0], a0, b0[0], b0[1]);
        mma16816h(c[0][1], a0, b0[2], b0[3]);
        mma16816h(c[0][2], a0, b1[0], b1[1]);
        mma16816h(c[0][3], a0, b1[2], b1[3]);
        mma16816h(c[1][0], a1, b0[0], b0[1]);
        mma16816h(c[1][1], a1, b0[2], b0[3]);
        mma16816h(c[1][2], a1, b1[0], b1[1]);
        mma16816h(c[1][3], a1, b1[2], b1[3]);
    }

    const int crow = lane >> 2;
    const int ccol = (lane & 3) * 2;
#pragma unroll
    for (int mi = 0; mi < 2; mi++) {
#pragma unroll
        for (int ni = 0; ni < 4; ni++) {
            int colg = warpCol + ni * 8 + ccol;
            int r0 = rbase + warpRow + mi * 16 + crow;
            int r1 = r0 + 8;
            if (outFloat) {
                float bx = bias[colg], by = bias[colg + 1];
                if (r0 < M) {
                    float2 v = make_float2(c[mi][ni][0] + bx, c[mi][ni][1] + by);
                    *reinterpret_cast<float2*>(Cf + (size_t)r0 * FDIM + colg) = v;
                }
                if (r1 < M) {
                    float2 v = make_float2(c[mi][ni][2] + bx, c[mi][ni][3] + by);
                    *reinterpret_cast<float2*>(Cf + (size_t)r1 * FDIM + colg) = v;
                }
            } else {
                if (r0 < M) {
                    __half2 v = __floats2half2_rn(c[mi][ni][0], c[mi][ni][1]);
                    *reinterpret_cast<__half2*>(Ch + (size_t)r0 * FDIM + colg) = v;
                }
                if (r1 < M) {
                    __half2 v = __floats2half2_rn(c[mi][ni][2], c[mi][ni][3]);
                    *reinterpret_cast<__half2*>(Ch + (size_t)r1 * FDIM + colg) = v;
                }
            }
        }
    }
}

// ---------------- CSR aggregate: fp16 gathers -> fp16 out ----------------

__global__ void __launch_bounds__(256) k_aggregate(
    const int* __restrict__ rowptr, const int* __restrict__ srow,
    const float* __restrict__ snorm, const float* __restrict__ dinv,
    const float* __restrict__ bias, const __half* __restrict__ t16,
    __half* __restrict__ h16, int n, int doRelu)
{
    int node = blockIdx.x * 8 + (threadIdx.x >> 5);
    if (node >= n) return;
    const int lane = threadIdx.x & 31;
    const int f4 = lane * 4;

    float d = __ldg(dinv + node);
    float d2 = d * d;

    uint2 sraw = *reinterpret_cast<const uint2*>(t16 + (size_t)node * FDIM + f4);
    float2 s0 = __half22float2(*reinterpret_cast<__half2*>(&sraw.x));
    float2 s1 = __half22float2(*reinterpret_cast<__half2*>(&sraw.y));
    float4 bv = *reinterpret_cast<const float4*>(bias + f4);
    float4 acc;
    acc.x = fmaf(s0.x, d2, bv.x);
    acc.y = fmaf(s0.y, d2, bv.y);
    acc.z = fmaf(s1.x, d2, bv.z);
    acc.w = fmaf(s1.y, d2, bv.w);

    int j = __ldg(rowptr + node);
    const int jend = __ldg(rowptr + node + 1);

#define GATHER(rj, wj)                                                          \
    do {                                                                        \
        uint2 raw = *reinterpret_cast<const uint2*>(t16 + (size_t)(rj) * FDIM + f4); \
        float2 p0 = __half22float2(*reinterpret_cast<__half2*>(&raw.x));        \
        float2 p1 = __half22float2(*reinterpret_cast<__half2*>(&raw.y));        \
        acc.x = fmaf(p0.x, (wj), acc.x); acc.y = fmaf(p0.y, (wj), acc.y);       \
        acc.z = fmaf(p1.x, (wj), acc.z); acc.w = fmaf(p1.y, (wj), acc.w);       \
    } while (0)

    for (; j + 3 < jend; j += 4) {
        int r0 = __ldg(srow + j);
        int r1 = __ldg(srow + j + 1);
        int r2 = __ldg(srow + j + 2);
        int r3 = __ldg(srow + j + 3);
        float w0 = __ldg(snorm + j);
        float w1 = __ldg(snorm + j + 1);
        float w2 = __ldg(snorm + j + 2);
        float w3 = __ldg(snorm + j + 3);
        GATHER(r0, w0);
        GATHER(r1, w1);
        GATHER(r2, w2);
        GATHER(r3, w3);
    }
    for (; j < jend; j++) {
        int r0 = __ldg(srow + j);
        float w0 = __ldg(snorm + j);
        GATHER(r0, w0);
    }
#undef GATHER

    if (doRelu) {
        acc.x = fmaxf(acc.x, 0.f); acc.y = fmaxf(acc.y, 0.f);
        acc.z = fmaxf(acc.z, 0.f); acc.w = fmaxf(acc.w, 0.f);
    }
    __half2 o0 = __floats2half2_rn(acc.x, acc.y);
    __half2 o1 = __floats2half2_rn(acc.z, acc.w);
    uint2 o;
    o.x = *reinterpret_cast<uint32_t*>(&o0);
    o.y = *reinterpret_cast<uint32_t*>(&o1);
    *reinterpret_cast<uint2*>(h16 + (size_t)node * FDIM + f4) = o;
}

// ---------------- launch ----------------

extern "C" void kernel_launch(void* const* d_in, const int* in_sizes, int n_in,
                              void* d_out, int out_size) {
    const float* x    = (const float*)d_in[0];
    const int*   ei   = (const int*)  d_in[1];
    const float* ew   = (const float*)d_in[2];
    const float* Wc[4] = {(const float*)d_in[3], (const float*)d_in[5],
                          (const float*)d_in[7], (const float*)d_in[9]};
    const float* bc[4] = {(const float*)d_in[4], (const float*)d_in[6],
                          (const float*)d_in[8], (const float*)d_in[10]};
    const float* Wout = (const float*)d_in[11];
    const float* bout = (const float*)d_in[12];
    float* out = (float*)d_out;

    const int N = in_sizes[0] / FDIM;
    const int E = in_sizes[2];
    const int* rowp = ei;
    const int* colp = ei + E;

    float *deg, *dinv, *snorm;
    int *cnt, *rowptr, *cur, *srow, *bsum, *boffs;
    __half *t16, *h16, *x16, *w16;
    cudaGetSymbolAddress((void**)&t16, g_t16);
    cudaGetSymbolAddress((void**)&h16, g_h16);
    cudaGetSymbolAddress((void**)&x16, g_x16);
    cudaGetSymbolAddress((void**)&deg, g_deg);
    cudaGetSymbolAddress((void**)&dinv, g_dinv);
    cudaGetSymbolAddress((void**)&cnt, g_cnt);
    cudaGetSymbolAddress((void**)&rowptr, g_rowptr);
    cudaGetSymbolAddress((void**)&cur, g_cursor);
    cudaGetSymbolAddress((void**)&srow, g_srow);
    cudaGetSymbolAddress((void**)&snorm, g_snorm);
    cudaGetSymbolAddress((void**)&bsum, g_bsum);
    cudaGetSymbolAddress((void**)&boffs, g_boffs);
    cudaGetSymbolAddress((void**)&w16, g_w16);

    static const int SMEM_DYN = 49152;
    cudaFuncSetAttribute(k_gemm_mma, cudaFuncAttributeMaxDynamicSharedMemorySize, SMEM_DYN);

    static cudaStream_t s2 = nullptr;
    static cudaEvent_t eFork = nullptr, eJoin = nullptr;
    if (s2 == nullptr) {
        cudaStreamCreateWithFlags(&s2, cudaStreamNonBlocking);
        cudaEventCreateWithFlags(&eFork, cudaEventDisableTiming);
        cudaEventCreateWithFlags(&eJoin, cudaEventDisableTiming);
    }

    const int TB = 256;
    const int nScanBlk = (N + SCAN_B - 1) / SCAN_B;
    const int wpBlocks = (16384 + TB - 1) / TB;
    const int gemmBlocks = (N + BM - 1) / BM;
    const int aggBlocks  = (N + 7) / 8;
    const int xpBlocks   = (N * 32 + TB - 1) / TB;

    // ---- main stream: GEMM-0 chain (gemm is launch #4 for ncu) ----
    k_wprep<<<wpBlocks, TB>>>(Wc[0], w16);                                     // #1
    k_xprep<<<xpBlocks, TB>>>(x, x16, N * 32);                                 // #2

    cudaEventRecord(eFork, 0);
    cudaStreamWaitEvent(s2, eFork, 0);

    k_init<<<(N + TB - 1) / TB, TB, 0, s2>>>(deg, cnt, cur, N);                // #3
    k_gemm_mma<<<gemmBlocks, TB, SMEM_DYN>>>(x16, w16,
                                             nullptr, t16, nullptr, N, 0);     // #4 <- profiled
    // ---- side stream: CSR build chain ----
    k_deg_hist<<<(E + TB - 1) / TB, TB, 0, s2>>>(colp, ew, deg, cnt, E);
    k_dinv<<<(N + TB - 1) / TB, TB, 0, s2>>>(deg, dinv, N);
    k_scan_local<<<nScanBlk, SCAN_B, 0, s2>>>(cnt, rowptr, bsum, N);
    k_scan_mid<<<1, MAXBLK, 0, s2>>>(bsum, boffs, nScanBlk);
    k_scan_add<<<nScanBlk, SCAN_B, 0, s2>>>(rowptr, boffs, N, E);
    k_fill<<<(E + TB - 1) / TB, TB, 0, s2>>>(rowp, colp, ew, dinv, rowptr,
                                             cur, srow, snorm, E);
    {
        dim3 wg(wpBlocks, 4);
        k_wprep4<<<wg, TB, 0, s2>>>(Wc[1], Wc[2], Wc[3], Wout, w16);
    }
    cudaEventRecord(eJoin, s2);
    cudaStreamWaitEvent(0, eJoin, 0);

    // ---- layers ----
    k_aggregate<<<aggBlocks, TB>>>(rowptr, srow, snorm, dinv, bc[0], t16,
                                   h16, N, 1);
    for (int l = 1; l < 4; l++) {
        k_gemm_mma<<<gemmBlocks, TB, SMEM_DYN>>>(h16, w16 + l * 16384,
                                                 nullptr, t16, nullptr, N, 0);
        k_aggregate<<<aggBlocks, TB>>>(rowptr, srow, snorm, dinv, bc[l], t16,
                                       h16, N, (l < 3) ? 1 : 0);
    }

    k_gemm_mma<<<gemmBlocks, TB, SMEM_DYN>>>(h16, w16 + 4 * 16384,
                                             bout, nullptr, out, N, 1);
}

// round 16
// speedup vs baseline: 1.0350x; 1.0350x over previous
#include <cuda_runtime.h>
#include <cuda_bf16.h>
#include <cuda_fp16.h>
#include <cstdint>

// ---------------------------------------------------------------------------
// GCN: 4x GCNConv(128->128) + output linear(128->128), N=100000, E=1600000.
// Round 16: GEMM warp tile 32x64 (BM=128, 8 warps 4x2): 6 ldsm / 16 mma per
// k-step (was 4/8) — L1/ldsm path was the invariant bound (occ proven moot).
// ---------------------------------------------------------------------------

#define NMAX 100096
#define EMAX 1600000
#define FDIM 128
#define SCAN_B 1024
#define MAXBLK 128
#define BM 128

__device__ __align__(16) __half g_t16[(size_t)NMAX * FDIM];   // conv GEMM out
__device__ __align__(16) __half g_h16[(size_t)NMAX * FDIM];   // aggregate out
__device__ __align__(16) __half g_x16[(size_t)NMAX * FDIM];   // fp16 input x
__device__ float g_deg[NMAX];
__device__ float g_dinv[NMAX];
__device__ int   g_cnt[NMAX];
__device__ int   g_rowptr[NMAX + 1];
__device__ int   g_cursor[NMAX];
__device__ int   g_srow[EMAX];
__device__ float g_snorm[EMAX];
__device__ int   g_bsum[MAXBLK];
__device__ int   g_boffs[MAXBLK];
__device__ __align__(16) __half g_w16[5 * 16384];

// ---------------- helpers ----------------

__device__ __forceinline__ uint32_t smem_u32(const void* p) {
    uint32_t a;
    asm("{ .reg .u64 t; cvta.to.shared.u64 t, %1; cvt.u32.u64 %0, t; }" : "=r"(a) : "l"(p));
    return a;
}

__device__ __forceinline__ void ldsm4(uint32_t& r0, uint32_t& r1, uint32_t& r2,
                                      uint32_t& r3, uint32_t addr) {
    asm volatile("ldmatrix.sync.aligned.m8n8.x4.shared.b16 {%0,%1,%2,%3}, [%4];"
                 : "=r"(r0), "=r"(r1), "=r"(r2), "=r"(r3) : "r"(addr));
}

__device__ __forceinline__ void mma16816h(float* c, const uint32_t* a,
                                          uint32_t b0, uint32_t b1) {
    asm volatile(
        "mma.sync.aligned.m16n8k16.row.col.f32.f16.f16.f32 "
        "{%0,%1,%2,%3}, {%4,%5,%6,%7}, {%8,%9}, {%0,%1,%2,%3};"
        : "+f"(c[0]), "+f"(c[1]), "+f"(c[2]), "+f"(c[3])
        : "r"(a[0]), "r"(a[1]), "r"(a[2]), "r"(a[3]), "r"(b0), "r"(b1));
}

__device__ __forceinline__ void cp16(uint32_t dst, const void* src) {
    asm volatile("cp.async.ca.shared.global [%0], [%1], 16;" :: "r"(dst), "l"(src));
}

__device__ __forceinline__ uint32_t swz(int r, int k) {
    return (uint32_t)((r << 8) + ((((k >> 3) ^ (r & 7)) << 4)) + ((k & 7) << 1));
}

// ---------------- x prep: fp32 -> fp16 ----------------

__global__ void k_xprep(const float* __restrict__ x, __half* __restrict__ x16,
                        int total4) {
    int i = blockIdx.x * blockDim.x + threadIdx.x;
    if (i >= total4) return;
    float4 v = reinterpret_cast<const float4*>(x)[i];
    __half2 p0 = __floats2half2_rn(v.x, v.y);
    __half2 p1 = __floats2half2_rn(v.z, v.w);
    uint2 o;
    o.x = *reinterpret_cast<uint32_t*>(&p0);
    o.y = *reinterpret_cast<uint32_t*>(&p1);
    reinterpret_cast<uint2*>(x16)[i] = o;
}

// ---------------- degree + histogram ----------------

__global__ void k_init(float* __restrict__ deg, int* __restrict__ cnt,
                       int* __restrict__ cur, int n) {
    int i = blockIdx.x * blockDim.x + threadIdx.x;
    if (i < n) { deg[i] = 1.0f; cnt[i] = 0; cur[i] = 0; }
}

__global__ void k_deg_hist(const int* __restrict__ col, const float* __restrict__ ew,
                           float* __restrict__ deg, int* __restrict__ cnt, int E) {
    int e = blockIdx.x * blockDim.x + threadIdx.x;
    if (e < E) {
        int c = col[e];
        atomicAdd(&deg[c], ew[e]);
        atomicAdd(&cnt[c], 1);
    }
}

__global__ void k_dinv(const float* __restrict__ deg, float* __restrict__ dinv, int n) {
    int i = blockIdx.x * blockDim.x + threadIdx.x;
    if (i < n) {
        float d = deg[i];
        dinv[i] = (d > 0.0f) ? rsqrtf(d) : 0.0f;
    }
}

// ---------------- 3-phase scan ----------------

__global__ void __launch_bounds__(SCAN_B) k_scan_local(
    const int* __restrict__ cnt, int* __restrict__ rowptr,
    int* __restrict__ bsum, int n)
{
    __shared__ int s[SCAN_B];
    const int tid = threadIdx.x;
    const int i = blockIdx.x * SCAN_B + tid;
    int v = (i < n) ? cnt[i] : 0;
    s[tid] = v;
    __syncthreads();
#pragma unroll
    for (int ofs = 1; ofs < SCAN_B; ofs <<= 1) {
        int t = (tid >= ofs) ? s[tid - ofs] : 0;
        __syncthreads();
        s[tid] += t;
        __syncthreads();
    }
    if (i < n) rowptr[i] = s[tid] - v;
    if (tid == SCAN_B - 1) bsum[blockIdx.x] = s[tid];
}

__global__ void __launch_bounds__(MAXBLK) k_scan_mid(
    const int* __restrict__ bsum, int* __restrict__ boffs, int nb)
{
    __shared__ int s[MAXBLK];
    const int tid = threadIdx.x;
    int v = (tid < nb) ? bsum[tid] : 0;
    s[tid] = v;
    __syncthreads();
#pragma unroll
    for (int ofs = 1; ofs < MAXBLK; ofs <<= 1) {
        int t = (tid >= ofs) ? s[tid - ofs] : 0;
        __syncthreads();
        s[tid] += t;
        __syncthreads();
    }
    if (tid < nb) boffs[tid] = s[tid] - v;
}

__global__ void __launch_bounds__(SCAN_B) k_scan_add(
    int* __restrict__ rowptr, const int* __restrict__ boffs, int n, int E)
{
    const int i = blockIdx.x * SCAN_B + threadIdx.x;
    if (i < n) rowptr[i] += boffs[blockIdx.x];
    if (i == 0) rowptr[n] = E;
}

// ---------------- counting-sort fill ----------------

__global__ void k_fill(const int* __restrict__ row, const int* __restrict__ col,
                       const float* __restrict__ ew, const float* __restrict__ dinv,
                       const int* __restrict__ rowptr, int* __restrict__ cur,
                       int* __restrict__ srow, float* __restrict__ snorm, int E) {
    int e = blockIdx.x * blockDim.x + threadIdx.x;
    if (e >= E) return;
    int r = row[e];
    int c = col[e];
    int pos = rowptr[c] + atomicAdd(&cur[c], 1);
    srow[pos] = r;
    snorm[pos] = dinv[r] * ew[e] * dinv[c];
}

// ---------------- weight prep: single fp16 ----------------

__device__ __forceinline__ void wprep_one(const float* W, __half* dst, int idx) {
    int n = idx >> 7, k = idx & 127;
    dst[n * 128 + k] = __float2half_rn(W[k * 128 + n]);   // B[n][k] = W[k][n]
}

__global__ void k_wprep(const float* __restrict__ W, __half* __restrict__ dst) {
    int idx = blockIdx.x * blockDim.x + threadIdx.x;
    if (idx >= 16384) return;
    wprep_one(W, dst, idx);
}

__global__ void k_wprep4(const float* __restrict__ W1, const float* __restrict__ W2,
                         const float* __restrict__ W3, const float* __restrict__ W4,
                         __half* __restrict__ base) {
    int idx = blockIdx.x * blockDim.x + threadIdx.x;
    if (idx >= 16384) return;
    const float* W = (blockIdx.y == 0) ? W1 : (blockIdx.y == 1) ? W2
                   : (blockIdx.y == 2) ? W3 : W4;
    wprep_one(W, base + (blockIdx.y + 1) * 16384, idx);
}

// ---------------- fp16 HMMA GEMM: C = A @ W ----------------
// BM=128, 8 warps 4x2 (32x64 per warp); 6 ldsm / 16 mma per k-step.

__global__ void __launch_bounds__(256, 2) k_gemm_mma(
    const __half* __restrict__ A, const __half* __restrict__ w16,
    const float* __restrict__ bias, __half* __restrict__ Ch,
    float* __restrict__ Cf, int M, int outFloat)
{
    extern __shared__ char sm[];
    char* sA = sm;                    // 128 rows x 256B = 32KB
    char* sW = sm + 32768;            // 32KB

    const int tid = threadIdx.x;
    const int wid = tid >> 5;
    const int lane = tid & 31;
    const int rbase = blockIdx.x * BM;

    const uint32_t uA = smem_u32(sA);
    const uint32_t uW = smem_u32(sW);

    for (int i = tid; i < 2048; i += 256) {
        int r = i >> 4, c = i & 15;
        uint32_t doff = (uint32_t)((r << 8) + ((c ^ (r & 7)) << 4));
        cp16(uW + doff, w16 + r * 128 + c * 8);
    }
    for (int i = tid; i < 2048; i += 256) {
        int r = i >> 4, c = i & 15;
        int grow = rbase + r;
        if (grow < M) {
            uint32_t doff = (uint32_t)((r << 8) + ((c ^ (r & 7)) << 4));
            cp16(uA + doff, A + (size_t)grow * FDIM + c * 8);
        }
    }
    asm volatile("cp.async.commit_group;" ::: "memory");
    asm volatile("cp.async.wait_group 0;" ::: "memory");
    __syncthreads();

    const int warpRow = (wid & 3) * 32;   // 4 row groups of 32
    const int warpCol = (wid >> 2) * 64;  // 2 col groups of 64
    const int a_r = lane & 15;
    const int a_k = (lane >> 4) << 3;
    const int b_n = (lane & 7) + ((lane >> 4) << 3);
    const int b_k = ((lane >> 3) & 1) << 3;

    float c[2][8][4];
#pragma unroll
    for (int mi = 0; mi < 2; mi++)
#pragma unroll
        for (int ni = 0; ni < 8; ni++)
#pragma unroll
            for (int q = 0; q < 4; q++) c[mi][ni][q] = 0.0f;

    uint32_t a0[4], a1[4], b[4][4];

#pragma unroll
    for (int it = 0; it < 8; it++) {
        const int k0 = it << 4;
        ldsm4(a0[0], a0[1], a0[2], a0[3], uA + swz(warpRow + a_r,      k0 + a_k));
        ldsm4(a1[0], a1[1], a1[2], a1[3], uA + swz(warpRow + 16 + a_r, k0 + a_k));
#pragma unroll
        for (int g = 0; g < 4; g++)
            ldsm4(b[g][0], b[g][1], b[g][2], b[g][3],
                  uW + swz(warpCol + g * 16 + b_n, k0 + b_k));
#pragma unroll
        for (int g = 0; g < 4; g++) {
            mma16816h(c[0][g * 2],     a0, b[g][0], b[g][1]);
            mma16816h(c[0][g * 2 + 1], a0, b[g][2], b[g][3]);
            mma16816h(c[1][g * 2],     a1, b[g][0], b[g][1]);
            mma16816h(c[1][g * 2 + 1], a1, b[g][2], b[g][3]);
        }
    }

    const int crow = lane >> 2;
    const int ccol = (lane & 3) * 2;
#pragma unroll
    for (int mi = 0; mi < 2; mi++) {
#pragma unroll
        for (int ni = 0; ni < 8; ni++) {
            int colg = warpCol + ni * 8 + ccol;
            int r0 = rbase + warpRow + mi * 16 + crow;
            int r1 = r0 + 8;
            if (outFloat) {
                float bx = bias[colg], by = bias[colg + 1];
                if (r0 < M) {
                    float2 v = make_float2(c[mi][ni][0] + bx, c[mi][ni][1] + by);
                    *reinterpret_cast<float2*>(Cf + (size_t)r0 * FDIM + colg) = v;
                }
                if (r1 < M) {
                    float2 v = make_float2(c[mi][ni][2] + bx, c[mi][ni][3] + by);
                    *reinterpret_cast<float2*>(Cf + (size_t)r1 * FDIM + colg) = v;
                }
            } else {
                if (r0 < M) {
                    __half2 v = __floats2half2_rn(c[mi][ni][0], c[mi][ni][1]);
                    *reinterpret_cast<__half2*>(Ch + (size_t)r0 * FDIM + colg) = v;
                }
                if (r1 < M) {
                    __half2 v = __floats2half2_rn(c[mi][ni][2], c[mi][ni][3]);
                    *reinterpret_cast<__half2*>(Ch + (size_t)r1 * FDIM + colg) = v;
                }
            }
        }
    }
}

// ---------------- CSR aggregate: fp16 gathers -> fp16 out ----------------

__global__ void __launch_bounds__(256) k_aggregate(
    const int* __restrict__ rowptr, const int* __restrict__ srow,
    const float* __restrict__ snorm, const float* __restrict__ dinv,
    const float* __restrict__ bias, const __half* __restrict__ t16,
    __half* __restrict__ h16, int n, int doRelu)
{
    int node = blockIdx.x * 8 + (threadIdx.x >> 5);
    if (node >= n) return;
    const int lane = threadIdx.x & 31;
    const int f4 = lane * 4;

    float d = __ldg(dinv + node);
    float d2 = d * d;

    uint2 sraw = *reinterpret_cast<const uint2*>(t16 + (size_t)node * FDIM + f4);
    float2 s0 = __half22float2(*reinterpret_cast<__half2*>(&sraw.x));
    float2 s1 = __half22float2(*reinterpret_cast<__half2*>(&sraw.y));
    float4 bv = *reinterpret_cast<const float4*>(bias + f4);
    float4 acc;
    acc.x = fmaf(s0.x, d2, bv.x);
    acc.y = fmaf(s0.y, d2, bv.y);
    acc.z = fmaf(s1.x, d2, bv.z);
    acc.w = fmaf(s1.y, d2, bv.w);

    int j = __ldg(rowptr + node);
    const int jend = __ldg(rowptr + node + 1);

#define GATHER(rj, wj)                                                          \
    do {                                                                        \
        uint2 raw = *reinterpret_cast<const uint2*>(t16 + (size_t)(rj) * FDIM + f4); \
        float2 p0 = __half22float2(*reinterpret_cast<__half2*>(&raw.x));        \
        float2 p1 = __half22float2(*reinterpret_cast<__half2*>(&raw.y));        \
        acc.x = fmaf(p0.x, (wj), acc.x); acc.y = fmaf(p0.y, (wj), acc.y);       \
        acc.z = fmaf(p1.x, (wj), acc.z); acc.w = fmaf(p1.y, (wj), acc.w);       \
    } while (0)

    for (; j + 3 < jend; j += 4) {
        int r0 = __ldg(srow + j);
        int r1 = __ldg(srow + j + 1);
        int r2 = __ldg(srow + j + 2);
        int r3 = __ldg(srow + j + 3);
        float w0 = __ldg(snorm + j);
        float w1 = __ldg(snorm + j + 1);
        float w2 = __ldg(snorm + j + 2);
        float w3 = __ldg(snorm + j + 3);
        GATHER(r0, w0);
        GATHER(r1, w1);
        GATHER(r2, w2);
        GATHER(r3, w3);
    }
    for (; j < jend; j++) {
        int r0 = __ldg(srow + j);
        float w0 = __ldg(snorm + j);
        GATHER(r0, w0);
    }
#undef GATHER

    if (doRelu) {
        acc.x = fmaxf(acc.x, 0.f); acc.y = fmaxf(acc.y, 0.f);
        acc.z = fmaxf(acc.z, 0.f); acc.w = fmaxf(acc.w, 0.f);
    }
    __half2 o0 = __floats2half2_rn(acc.x, acc.y);
    __half2 o1 = __floats2half2_rn(acc.z, acc.w);
    uint2 o;
    o.x = *reinterpret_cast<uint32_t*>(&o0);
    o.y = *reinterpret_cast<uint32_t*>(&o1);
    *reinterpret_cast<uint2*>(h16 + (size_t)node * FDIM + f4) = o;
}

// ---------------- launch ----------------

extern "C" void kernel_launch(void* const* d_in, const int* in_sizes, int n_in,
                              void* d_out, int out_size) {
    const float* x    = (const float*)d_in[0];
    const int*   ei   = (const int*)  d_in[1];
    const float* ew   = (const float*)d_in[2];
    const float* Wc[4] = {(const float*)d_in[3], (const float*)d_in[5],
                          (const float*)d_in[7], (const float*)d_in[9]};
    const float* bc[4] = {(const float*)d_in[4], (const float*)d_in[6],
                          (const float*)d_in[8], (const float*)d_in[10]};
    const float* Wout = (const float*)d_in[11];
    const float* bout = (const float*)d_in[12];
    float* out = (float*)d_out;

    const int N = in_sizes[0] / FDIM;
    const int E = in_sizes[2];
    const int* rowp = ei;
    const int* colp = ei + E;

    float *deg, *dinv, *snorm;
    int *cnt, *rowptr, *cur, *srow, *bsum, *boffs;
    __half *t16, *h16, *x16, *w16;
    cudaGetSymbolAddress((void**)&t16, g_t16);
    cudaGetSymbolAddress((void**)&h16, g_h16);
    cudaGetSymbolAddress((void**)&x16, g_x16);
    cudaGetSymbolAddress((void**)&deg, g_deg);
    cudaGetSymbolAddress((void**)&dinv, g_dinv);
    cudaGetSymbolAddress((void**)&cnt, g_cnt);
    cudaGetSymbolAddress((void**)&rowptr, g_rowptr);
    cudaGetSymbolAddress((void**)&cur, g_cursor);
    cudaGetSymbolAddress((void**)&srow, g_srow);
    cudaGetSymbolAddress((void**)&snorm, g_snorm);
    cudaGetSymbolAddress((void**)&bsum, g_bsum);
    cudaGetSymbolAddress((void**)&boffs, g_boffs);
    cudaGetSymbolAddress((void**)&w16, g_w16);

    static const int SMEM_DYN = 65536;
    cudaFuncSetAttribute(k_gemm_mma, cudaFuncAttributeMaxDynamicSharedMemorySize, SMEM_DYN);

    static cudaStream_t s2 = nullptr;
    static cudaEvent_t eFork = nullptr, eJoin = nullptr;
    if (s2 == nullptr) {
        cudaStreamCreateWithFlags(&s2, cudaStreamNonBlocking);
        cudaEventCreateWithFlags(&eFork, cudaEventDisableTiming);
        cudaEventCreateWithFlags(&eJoin, cudaEventDisableTiming);
    }

    const int TB = 256;
    const int nScanBlk = (N + SCAN_B - 1) / SCAN_B;
    const int wpBlocks = (16384 + TB - 1) / TB;
    const int gemmBlocks = (N + BM - 1) / BM;
    const int aggBlocks  = (N + 7) / 8;
    const int xpBlocks   = (N * 32 + TB - 1) / TB;

    // ---- main stream: GEMM-0 chain (gemm is launch #4 for ncu) ----
    k_wprep<<<wpBlocks, TB>>>(Wc[0], w16);                                     // #1
    k_xprep<<<xpBlocks, TB>>>(x, x16, N * 32);                                 // #2

    cudaEventRecord(eFork, 0);
    cudaStreamWaitEvent(s2, eFork, 0);

    k_init<<<(N + TB - 1) / TB, TB, 0, s2>>>(deg, cnt, cur, N);                // #3
    k_gemm_mma<<<gemmBlocks, TB, SMEM_DYN>>>(x16, w16,
                                             nullptr, t16, nullptr, N, 0);     // #4 <- profiled
    // ---- side stream: CSR build chain ----
    k_deg_hist<<<(E + TB - 1) / TB, TB, 0, s2>>>(colp, ew, deg, cnt, E);
    k_dinv<<<(N + TB - 1) / TB, TB, 0, s2>>>(deg, dinv, N);
    k_scan_local<<<nScanBlk, SCAN_B, 0, s2>>>(cnt, rowptr, bsum, N);
    k_scan_mid<<<1, MAXBLK, 0, s2>>>(bsum, boffs, nScanBlk);
    k_scan_add<<<nScanBlk, SCAN_B, 0, s2>>>(rowptr, boffs, N, E);
    k_fill<<<(E + TB - 1) / TB, TB, 0, s2>>>(rowp, colp, ew, dinv, rowptr,
                                             cur, srow, snorm, E);
    {
        dim3 wg(wpBlocks, 4);
        k_wprep4<<<wg, TB, 0, s2>>>(Wc[1], Wc[2], Wc[3], Wout, w16);
    }
    cudaEventRecord(eJoin, s2);
    cudaStreamWaitEvent(0, eJoin, 0);

    // ---- layers ----
    k_aggregate<<<aggBlocks, TB>>>(rowptr, srow, snorm, dinv, bc[0], t16,
                                   h16, N, 1);
    for (int l = 1; l < 4; l++) {
        k_gemm_mma<<<gemmBlocks, TB, SMEM_DYN>>>(h16, w16 + l * 16384,
                                                 nullptr, t16, nullptr, N, 0);
        k_aggregate<<<aggBlocks, TB>>>(rowptr, srow, snorm, dinv, bc[l], t16,
                                       h16, N, (l < 3) ? 1 : 0);
    }

    k_gemm_mma<<<gemmBlocks, TB, SMEM_DYN>>>(h16, w16 + 4 * 16384,
                                             bout, nullptr, out, N, 1);
}